// round 9
// baseline (speedup 1.0000x reference)
#include <cuda_runtime.h>
#include <cuda_fp16.h>
#include <math_constants.h>
#include <stdint.h>

#define NROWS  32768
#define DIM    256
#define KCODES 8192

#define BM 128
#define BN 32
#define NTILES (KCODES / BN)   // 256
#define WINDOW 4.0f            // scaled-dot domain (dot * 4096)

#define RSTRIDE 528            // 256 f16 = 512B + 16B pad (16B-aligned LDS.128)
#define XS_OFF 0
#define XS_SZ  (BM * RSTRIDE)              // 67584
#define WB_OFF XS_SZ
#define WB_SZ  (BN * RSTRIDE)              // 16896
#define SMEM_TOTAL (XS_SZ + 2 * WB_SZ)     // 101376

// merge area reuses dead X/W regions after the main loop
#define CAND_OFF     0                     // 128 rows * 16 writers * 3 ents * 8B = 49152
#define OVF_LIST_OFF 49152
#define OVF_CNT_OFF  (OVF_LIST_OFF + 128 * 4)

__device__ float  g_a[NROWS];
__device__ float  g_c[KCODES];
__device__ int    g_idx[NROWS];
__device__ __align__(16) __half g_xh[NROWS * DIM];
__device__ __align__(16) __half g_wh[KCODES * DIM];   // W * 4096

// ---------------- asm helpers ----------------
__device__ __forceinline__ uint32_t smem_u32(const void* p) {
    uint32_t a;
    asm("{ .reg .u64 t; cvta.to.shared.u64 t, %1; cvt.u32.u64 %0, t; }" : "=r"(a) : "l"(p));
    return a;
}
__device__ __forceinline__ void cp16(uint32_t s, const void* g) {
    asm volatile("cp.async.cg.shared.global [%0], [%1], 16;" :: "r"(s), "l"(g));
}
#define CP_COMMIT() asm volatile("cp.async.commit_group;" ::: "memory")
#define CP_WAIT0()  asm volatile("cp.async.wait_group 0;" ::: "memory")
#define CP_WAIT1()  asm volatile("cp.async.wait_group 1;" ::: "memory")

// ---------------- prep kernels (proven: rel_err 0.0 in rounds 4-7) ----------------
__global__ void vq_prep_x(const float* __restrict__ x, float* __restrict__ a,
                          __half* __restrict__ xh) {
    int warp = (blockIdx.x * blockDim.x + threadIdx.x) >> 5;
    int lane = threadIdx.x & 31;
    if (warp >= NROWS) return;
    const float4* r4 = (const float4*)(x + (size_t)warp * DIM);
    float4 v0 = r4[lane * 2 + 0], v1 = r4[lane * 2 + 1];
    float s = 0.f;
    s = fmaf(v0.x, v0.x, s); s = fmaf(v0.y, v0.y, s); s = fmaf(v0.z, v0.z, s); s = fmaf(v0.w, v0.w, s);
    s = fmaf(v1.x, v1.x, s); s = fmaf(v1.y, v1.y, s); s = fmaf(v1.z, v1.z, s); s = fmaf(v1.w, v1.w, s);
    #pragma unroll
    for (int o = 16; o; o >>= 1) s += __shfl_xor_sync(0xffffffffu, s, o);
    if (lane == 0) a[warp] = s;
    __half2 h0 = __floats2half2_rn(v0.x, v0.y), h1 = __floats2half2_rn(v0.z, v0.w);
    __half2 h2 = __floats2half2_rn(v1.x, v1.y), h3 = __floats2half2_rn(v1.z, v1.w);
    uint4 u;
    u.x = *(unsigned*)&h0; u.y = *(unsigned*)&h1; u.z = *(unsigned*)&h2; u.w = *(unsigned*)&h3;
    ((uint4*)(xh + (size_t)warp * DIM))[lane] = u;
}
__global__ void vq_prep_w(const float* __restrict__ w, float* __restrict__ c,
                          __half* __restrict__ wh) {
    int warp = (blockIdx.x * blockDim.x + threadIdx.x) >> 5;
    int lane = threadIdx.x & 31;
    if (warp >= KCODES) return;
    const float4* r4 = (const float4*)(w + (size_t)warp * DIM);
    float4 v0 = r4[lane * 2 + 0], v1 = r4[lane * 2 + 1];
    float s = 0.f;
    s = fmaf(v0.x, v0.x, s); s = fmaf(v0.y, v0.y, s); s = fmaf(v0.z, v0.z, s); s = fmaf(v0.w, v0.w, s);
    s = fmaf(v1.x, v1.x, s); s = fmaf(v1.y, v1.y, s); s = fmaf(v1.z, v1.z, s); s = fmaf(v1.w, v1.w, s);
    #pragma unroll
    for (int o = 16; o; o >>= 1) s += __shfl_xor_sync(0xffffffffu, s, o);
    if (lane == 0) c[warp] = s;
    const float SC = 4096.0f;
    __half2 h0 = __floats2half2_rn(v0.x * SC, v0.y * SC), h1 = __floats2half2_rn(v0.z * SC, v0.w * SC);
    __half2 h2 = __floats2half2_rn(v1.x * SC, v1.y * SC), h3 = __floats2half2_rn(v1.z * SC, v1.w * SC);
    uint4 u;
    u.x = *(unsigned*)&h0; u.y = *(unsigned*)&h1; u.z = *(unsigned*)&h2; u.w = *(unsigned*)&h3;
    ((uint4*)(wh + (size_t)warp * DIM))[lane] = u;
}

// ---------------- screen kernel (HFMA2, 256 thr, 2 CTA/SM) ----------------
__device__ __forceinline__ __half2 u2h(uint32_t v) {
    __half2 h;
    *(uint32_t*)&h = v;
    return h;
}

__global__ __launch_bounds__(256, 2)
void vq_screen(const float* __restrict__ X, const float* __restrict__ W,
               const __half* __restrict__ Xh, const __half* __restrict__ Wh) {
    extern __shared__ char smem[];
    const uint32_t sb = smem_u32(smem);
    const int tid = threadIdx.x;
    const int tx = tid & 15;        // code-group (2 codes per thread per tile)
    const int ty = tid >> 4;        // row-group  (8 rows per thread)
    const int wid = tid >> 5, lane = tid & 31;
    const int rBase = blockIdx.x * BM;

    // ---- prologue: X tile (whole CTA rows) + W tile 0, one commit group ----
    #pragma unroll
    for (int i = 0; i < 16; i++) {
        int idx = tid + i * 256;               // 0..4095
        int row = idx >> 5, c = idx & 31;
        cp16(sb + XS_OFF + row * RSTRIDE + c * 16,
             Xh + (size_t)(rBase + row) * DIM + c * 8);
    }
    #pragma unroll
    for (int i = 0; i < 4; i++) {
        int idx = tid + i * 256;               // 0..1023
        int row = idx >> 5, c = idx & 31;
        cp16(sb + WB_OFF + row * RSTRIDE + c * 16,
             Wh + (size_t)row * DIM + c * 8);
    }
    CP_COMMIT();

    // per-row top-2 + rest-max
    float v1[8], v2[8], v3[8];
    int   k1[8], k2[8];
    #pragma unroll
    for (int i = 0; i < 8; i++) {
        v1[i] = v2[i] = v3[i] = -CUDART_INF_F;
        k1[i] = k2[i] = 0;
    }

    const uint32_t xbase = sb + XS_OFF + (uint32_t)(ty * 8) * RSTRIDE;
    const uint32_t wrow0 = (uint32_t)(tx * 2) * RSTRIDE;

    for (int nt = 0; nt < NTILES; nt++) {
        __syncthreads();                         // close out reads of buf (nt-1)&1
        if (nt + 1 < NTILES) {
            uint32_t wb = sb + WB_OFF + (uint32_t)((nt + 1) & 1) * WB_SZ;
            #pragma unroll
            for (int i = 0; i < 4; i++) {
                int idx = tid + i * 256;
                int row = idx >> 5, c = idx & 31;
                cp16(wb + row * RSTRIDE + c * 16,
                     Wh + (size_t)((nt + 1) * BN + row) * DIM + c * 8);
            }
            CP_COMMIT();
            CP_WAIT1();
        } else {
            CP_WAIT0();
        }
        __syncthreads();                         // tile nt visible to all

        const uint32_t wb = sb + WB_OFF + (uint32_t)(nt & 1) * WB_SZ + wrow0;

        __half2 acc[8][2];
        #pragma unroll
        for (int i = 0; i < 8; i++) {
            acc[i][0] = __float2half2_rn(0.f);
            acc[i][1] = __float2half2_rn(0.f);
        }

        #pragma unroll 4
        for (int ks = 0; ks < DIM / 8; ks++) {   // 8 d's per step
            const uint32_t dof = (uint32_t)ks * 16;    // 8 f16 = 16B
            uint4 wv0 = *(const uint4*)(smem + (wb + dof) - sb);
            uint4 wv1 = *(const uint4*)(smem + (wb + RSTRIDE + dof) - sb);
            #pragma unroll
            for (int i = 0; i < 8; i++) {
                uint4 xv = *(const uint4*)(smem + (xbase + (uint32_t)i * RSTRIDE + dof) - sb);
                acc[i][0] = __hfma2(u2h(xv.x), u2h(wv0.x), acc[i][0]);
                acc[i][0] = __hfma2(u2h(xv.y), u2h(wv0.y), acc[i][0]);
                acc[i][0] = __hfma2(u2h(xv.z), u2h(wv0.z), acc[i][0]);
                acc[i][0] = __hfma2(u2h(xv.w), u2h(wv0.w), acc[i][0]);
                acc[i][1] = __hfma2(u2h(xv.x), u2h(wv1.x), acc[i][1]);
                acc[i][1] = __hfma2(u2h(xv.y), u2h(wv1.y), acc[i][1]);
                acc[i][1] = __hfma2(u2h(xv.z), u2h(wv1.z), acc[i][1]);
                acc[i][1] = __hfma2(u2h(xv.w), u2h(wv1.w), acc[i][1]);
            }
        }

        // ---- epilogue: top-2 + rest-max per row ----
        #pragma unroll
        for (int i = 0; i < 8; i++) {
            #pragma unroll
            for (int j = 0; j < 2; j++) {
                float2 f = __half22float2(acc[i][j]);
                float v = f.x + f.y;
                int kk = nt * BN + tx * 2 + j;
                if (v > v1[i]) {
                    v3[i] = fmaxf(v3[i], v2[i]);
                    v2[i] = v1[i]; k2[i] = k1[i];
                    v1[i] = v;     k1[i] = kk;
                } else if (v > v2[i]) {
                    v3[i] = fmaxf(v3[i], v2[i]);
                    v2[i] = v;     k2[i] = kk;
                } else {
                    v3[i] = fmaxf(v3[i], v);
                }
            }
        }
    }
    __syncthreads();   // all compute done before smem reuse

    // ---- merge candidates into smem ----
    float2* cand = (float2*)(smem + CAND_OFF);       // [row][16 writers][3]
    int* ovf_list = (int*)(smem + OVF_LIST_OFF);
    int* ovf_cnt  = (int*)(smem + OVF_CNT_OFF);
    #pragma unroll
    for (int i = 0; i < 8; i++) {
        int row = ty * 8 + i;
        float2* p = cand + ((size_t)row * 16 + tx) * 3;
        p[0] = make_float2(v1[i], __int_as_float(k1[i]));
        p[1] = make_float2(v2[i], __int_as_float(k2[i]));
        p[2] = make_float2(v3[i], __int_as_float(-1));
    }
    if (tid == 0) *ovf_cnt = 0;
    __syncthreads();

    // ---- per-row selection (one thread per row) ----
    if (tid < BM) {
        const int row = tid;
        const float2* p = cand + (size_t)row * 48;
        float rowmax = -CUDART_INF_F;
        for (int e = 0; e < 48; e++) rowmax = fmaxf(rowmax, p[e].x);
        const float th = rowmax - WINDOW;
        int sk[16]; int ns = 0; bool ovf = false;
        for (int e = 0; e < 48; e++) {
            if (p[e].x >= th) {
                int k = __float_as_int(p[e].y);
                if (k < 0) ovf = true;
                else if (ns < 16) sk[ns++] = k;
                else ovf = true;
            }
        }
        if (ovf) {
            int pos = atomicAdd(ovf_cnt, 1);
            ovf_list[pos] = row;
        } else {
            const int grow = rBase + row;
            int result = sk[0];
            if (ns > 1) {
                const float arow = g_a[grow];
                const float* xr = X + (size_t)grow * DIM;
                float best = CUDART_INF_F; int bestk = 0x7fffffff;
                for (int i = 0; i < ns; i++) {
                    int k = sk[i];
                    const float* wrp = W + (size_t)k * DIM;
                    float dot = 0.f;
                    #pragma unroll 8
                    for (int d = 0; d < DIM; d++) dot = fmaf(xr[d], wrp[d], dot);
                    float dist = fmaf(-2.f, dot, arow + g_c[k]);
                    if (dist < best || (dist == best && k < bestk)) { best = dist; bestk = k; }
                }
                result = bestk;
            }
            g_idx[grow] = result;
        }
    }
    __syncthreads();

    // ---- overflow rows (rare): exact full recheck, one warp per row ----
    int cnt = *ovf_cnt;
    for (int oi = wid; oi < cnt; oi += 8) {
        int row = ovf_list[oi];
        int grow = rBase + row;
        const float* xr = X + (size_t)grow * DIM;
        float arow = g_a[grow];
        float best = CUDART_INF_F; int bestk = 0x7fffffff;
        for (int kb = lane * 4; kb < KCODES; kb += 128) {
            const float* w0 = W + (size_t)(kb + 0) * DIM;
            const float* w1 = W + (size_t)(kb + 1) * DIM;
            const float* w2 = W + (size_t)(kb + 2) * DIM;
            const float* w3 = W + (size_t)(kb + 3) * DIM;
            float d0 = 0.f, d1 = 0.f, d2 = 0.f, d3 = 0.f;
            for (int d = 0; d < DIM; d++) {
                float xv = xr[d];
                d0 = fmaf(xv, w0[d], d0); d1 = fmaf(xv, w1[d], d1);
                d2 = fmaf(xv, w2[d], d2); d3 = fmaf(xv, w3[d], d3);
            }
            float dd[4];
            dd[0] = fmaf(-2.f, d0, arow + g_c[kb + 0]);
            dd[1] = fmaf(-2.f, d1, arow + g_c[kb + 1]);
            dd[2] = fmaf(-2.f, d2, arow + g_c[kb + 2]);
            dd[3] = fmaf(-2.f, d3, arow + g_c[kb + 3]);
            #pragma unroll
            for (int c = 0; c < 4; c++)
                if (dd[c] < best || (dd[c] == best && (kb + c) < bestk)) { best = dd[c]; bestk = kb + c; }
        }
        #pragma unroll
        for (int off = 16; off; off >>= 1) {
            float ob = __shfl_xor_sync(0xffffffffu, best, off);
            int   ok = __shfl_xor_sync(0xffffffffu, bestk, off);
            if (ob < best || (ob == best && ok < bestk)) { best = ob; bestk = ok; }
        }
        if (lane == 0) g_idx[grow] = bestk;
    }
}

// ---------------- gather ----------------
__global__ void vq_gather_kernel(const float* __restrict__ W,
                                 float* __restrict__ out,
                                 float* __restrict__ out_idx) {
    int warp = (blockIdx.x * blockDim.x + threadIdx.x) >> 5;
    int lane = threadIdx.x & 31;
    if (warp >= NROWS) return;
    int k = g_idx[warp];
    const float4* src = (const float4*)(W + (size_t)k * DIM);
    float4* dst = (float4*)(out + (size_t)warp * DIM);
    dst[lane]      = src[lane];
    dst[lane + 32] = src[lane + 32];
    if (out_idx != nullptr && lane == 0) out_idx[warp] = (float)k;
}

// ---------------- launcher ----------------
extern "C" void kernel_launch(void* const* d_in, const int* in_sizes, int n_in,
                              void* d_out, int out_size) {
    const float* X = (const float*)d_in[0];
    const float* W = (const float*)d_in[1];
    if (n_in >= 2 && in_sizes[0] == KCODES * DIM && in_sizes[1] == NROWS * DIM) {
        W = (const float*)d_in[0];
        X = (const float*)d_in[1];
    }
    float* out = (float*)d_out;

    float* pa = nullptr; float* pc = nullptr;
    __half* pxh = nullptr; __half* pwh = nullptr;
    cudaGetSymbolAddress((void**)&pa, g_a);
    cudaGetSymbolAddress((void**)&pc, g_c);
    cudaGetSymbolAddress((void**)&pxh, g_xh);
    cudaGetSymbolAddress((void**)&pwh, g_wh);

    cudaFuncSetAttribute(vq_screen, cudaFuncAttributeMaxDynamicSharedMemorySize, SMEM_TOTAL);

    vq_prep_x<<<NROWS / 8, 256>>>(X, pa, pxh);
    vq_prep_w<<<KCODES / 8, 256>>>(W, pc, pwh);
    vq_screen<<<NROWS / BM, 256, SMEM_TOTAL>>>(X, W, pxh, pwh);

    float* out_idx = (out_size >= NROWS * DIM + NROWS) ? (out + (size_t)NROWS * DIM) : nullptr;
    vq_gather_kernel<<<NROWS / 8, 256>>>(W, out, out_idx);
}

// round 10
// speedup vs baseline: 50.5965x; 50.5965x over previous
#include <cuda_runtime.h>
#include <cuda_fp16.h>
#include <math_constants.h>
#include <stdint.h>

#define NROWS  32768
#define DIM    256
#define KCODES 8192

#define BMH 96            // rows handled by HMMA warps (0-7)
#define BMF 32            // rows handled by FFMA warps (8-15)
#define BMT 128           // total rows per CTA
#define BN  128
#define NTILES (KCODES / BN)   // 64
#define WINDOW 0.75f           // scaled-dot domain (dot * 4096)

#define ASTRIDE 528
#define A_OFF 0
#define A_SZ  (BMH * ASTRIDE)              // 50688
#define B_OFF A_SZ
#define B_SZ  (BN * ASTRIDE)               // 67584
// FFMA engine regions (after both B buffers)
#define FF_XS (B_OFF + 2 * B_SZ)           // 185856: float[16][132]
#define FF_WS (FF_XS + 16 * 132 * 4)       // 194304: float[16][132]
#define FF_CS (FF_WS + 16 * 132 * 4)       // 202752: float[128]
#define FF_RD (FF_CS + 512)                // 203264: float[32]
#define FF_RK (FF_RD + 128)                // 203392: int[32]
#define SMEM_TOTAL (FF_RK + 128)           // 203520

// HMMA merge area reuses dead B buffers
#define CAND_OFF     B_OFF                 // 96 rows * 16 writers * 3 * 8B = 36864
#define OVF_LIST_OFF (B_OFF + 36864)
#define OVF_CNT_OFF  (OVF_LIST_OFF + 96 * 4)

__device__ float  g_a[NROWS];
__device__ float  g_c[KCODES];
__device__ int    g_idx[NROWS];
__device__ __align__(16) __half g_xh[NROWS * DIM];
__device__ __align__(16) __half g_wh[KCODES * DIM];   // W * 4096

// ---------------- asm helpers ----------------
__device__ __forceinline__ uint32_t smem_u32(const void* p) {
    uint32_t a;
    asm("{ .reg .u64 t; cvta.to.shared.u64 t, %1; cvt.u32.u64 %0, t; }" : "=r"(a) : "l"(p));
    return a;
}
__device__ __forceinline__ void cp16(uint32_t s, const void* g) {
    asm volatile("cp.async.cg.shared.global [%0], [%1], 16;" :: "r"(s), "l"(g));
}
#define CP_COMMIT() asm volatile("cp.async.commit_group;" ::: "memory")
#define CP_WAIT0()  asm volatile("cp.async.wait_group 0;" ::: "memory")
#define BAR1() asm volatile("bar.sync 1, 256;" ::: "memory")
#define BAR2() asm volatile("bar.sync 2, 256;" ::: "memory")

__device__ __forceinline__ void ldsm4(uint32_t addr, uint32_t& r0, uint32_t& r1,
                                      uint32_t& r2, uint32_t& r3) {
    asm volatile("ldmatrix.sync.aligned.m8n8.x4.shared.b16 {%0,%1,%2,%3}, [%4];"
                 : "=r"(r0), "=r"(r1), "=r"(r2), "=r"(r3) : "r"(addr));
}
__device__ __forceinline__ void mma16816(float* c, const uint32_t* a, const uint32_t* b) {
    asm volatile(
        "mma.sync.aligned.m16n8k16.row.col.f32.f16.f16.f32 "
        "{%0,%1,%2,%3}, {%4,%5,%6,%7}, {%8,%9}, {%0,%1,%2,%3};"
        : "+f"(c[0]), "+f"(c[1]), "+f"(c[2]), "+f"(c[3])
        : "r"(a[0]), "r"(a[1]), "r"(a[2]), "r"(a[3]), "r"(b[0]), "r"(b[1]));
}

// ---------------- prep kernels (proven) ----------------
__global__ void vq_prep_x(const float* __restrict__ x, float* __restrict__ a,
                          __half* __restrict__ xh) {
    int warp = (blockIdx.x * blockDim.x + threadIdx.x) >> 5;
    int lane = threadIdx.x & 31;
    if (warp >= NROWS) return;
    const float4* r4 = (const float4*)(x + (size_t)warp * DIM);
    float4 v0 = r4[lane * 2 + 0], v1 = r4[lane * 2 + 1];
    float s = 0.f;
    s = fmaf(v0.x, v0.x, s); s = fmaf(v0.y, v0.y, s); s = fmaf(v0.z, v0.z, s); s = fmaf(v0.w, v0.w, s);
    s = fmaf(v1.x, v1.x, s); s = fmaf(v1.y, v1.y, s); s = fmaf(v1.z, v1.z, s); s = fmaf(v1.w, v1.w, s);
    #pragma unroll
    for (int o = 16; o; o >>= 1) s += __shfl_xor_sync(0xffffffffu, s, o);
    if (lane == 0) a[warp] = s;
    __half2 h0 = __floats2half2_rn(v0.x, v0.y), h1 = __floats2half2_rn(v0.z, v0.w);
    __half2 h2 = __floats2half2_rn(v1.x, v1.y), h3 = __floats2half2_rn(v1.z, v1.w);
    uint4 u;
    u.x = *(unsigned*)&h0; u.y = *(unsigned*)&h1; u.z = *(unsigned*)&h2; u.w = *(unsigned*)&h3;
    ((uint4*)(xh + (size_t)warp * DIM))[lane] = u;
}
__global__ void vq_prep_w(const float* __restrict__ w, float* __restrict__ c,
                          __half* __restrict__ wh) {
    int warp = (blockIdx.x * blockDim.x + threadIdx.x) >> 5;
    int lane = threadIdx.x & 31;
    if (warp >= KCODES) return;
    const float4* r4 = (const float4*)(w + (size_t)warp * DIM);
    float4 v0 = r4[lane * 2 + 0], v1 = r4[lane * 2 + 1];
    float s = 0.f;
    s = fmaf(v0.x, v0.x, s); s = fmaf(v0.y, v0.y, s); s = fmaf(v0.z, v0.z, s); s = fmaf(v0.w, v0.w, s);
    s = fmaf(v1.x, v1.x, s); s = fmaf(v1.y, v1.y, s); s = fmaf(v1.z, v1.z, s); s = fmaf(v1.w, v1.w, s);
    #pragma unroll
    for (int o = 16; o; o >>= 1) s += __shfl_xor_sync(0xffffffffu, s, o);
    if (lane == 0) c[warp] = s;
    const float SC = 4096.0f;
    __half2 h0 = __floats2half2_rn(v0.x * SC, v0.y * SC), h1 = __floats2half2_rn(v0.z * SC, v0.w * SC);
    __half2 h2 = __floats2half2_rn(v1.x * SC, v1.y * SC), h3 = __floats2half2_rn(v1.z * SC, v1.w * SC);
    uint4 u;
    u.x = *(unsigned*)&h0; u.y = *(unsigned*)&h1; u.z = *(unsigned*)&h2; u.w = *(unsigned*)&h3;
    ((uint4*)(wh + (size_t)warp * DIM))[lane] = u;
}

// ---------------- hybrid screen kernel ----------------
__global__ __launch_bounds__(512, 1)
void vq_screen(const float* __restrict__ X, const float* __restrict__ W,
               const __half* __restrict__ Xh, const __half* __restrict__ Wh) {
    extern __shared__ char smem[];
    const uint32_t sb = smem_u32(smem);
    const int tid = threadIdx.x;
    const int wid = tid >> 5, lane = tid & 31;
    const int rBase = blockIdx.x * BMT;

    if (wid < 8) {
        // ================= HMMA engine: rows rBase .. rBase+95 =================
        const int warp_m = wid >> 2, warp_n = wid & 3;   // 2 x 4; warp tile 48x32
        const int g = lane >> 2, t = lane & 3;

        // prologue: A (96x512B) + B tile 0 via cp.async
        #pragma unroll
        for (int i = 0; i < 12; i++) {
            int idx = tid + i * 256;               // 0..3071
            int row = idx >> 5, c = idx & 31;
            cp16(sb + A_OFF + row * ASTRIDE + c * 16,
                 Xh + (size_t)(rBase + row) * DIM + c * 8);
        }
        #pragma unroll
        for (int i = 0; i < 16; i++) {
            int idx = tid + i * 256;
            int row = idx >> 5, c = idx & 31;
            cp16(sb + B_OFF + row * ASTRIDE + c * 16,
                 Wh + (size_t)row * DIM + c * 8);
        }
        CP_COMMIT();

        float cv1[6], cv2[6], cv3[6];
        int   ck1[6], ck2[6];
        #pragma unroll
        for (int s = 0; s < 6; s++) {
            cv1[s] = cv2[s] = cv3[s] = -CUDART_INF_F;
            ck1[s] = ck2[s] = 0;
        }

        const uint32_t a_base = sb + A_OFF +
            (uint32_t)(warp_m * 48 + (lane & 15)) * ASTRIDE + (uint32_t)(lane >> 4) * 16;
        const uint32_t b_row_off =
            (uint32_t)(warp_n * 32 + (lane & 7) + (lane >> 4) * 8) * ASTRIDE +
            (uint32_t)((lane >> 3) & 1) * 16;

        for (int nt = 0; nt < NTILES; nt++) {
            CP_WAIT0();
            BAR1();
            if (nt + 1 < NTILES) {
                int buf = (nt + 1) & 1;
                #pragma unroll
                for (int i = 0; i < 16; i++) {
                    int idx = tid + i * 256;
                    int row = idx >> 5, c = idx & 31;
                    cp16(sb + B_OFF + buf * B_SZ + row * ASTRIDE + c * 16,
                         Wh + (size_t)((nt + 1) * BN + row) * DIM + c * 8);
                }
                CP_COMMIT();
            }

            float acc[3][4][4];
            #pragma unroll
            for (int mi = 0; mi < 3; mi++)
                #pragma unroll
                for (int ni = 0; ni < 4; ni++)
                    #pragma unroll
                    for (int c = 0; c < 4; c++) acc[mi][ni][c] = 0.f;

            const uint32_t b_base = sb + B_OFF + (uint32_t)(nt & 1) * B_SZ + b_row_off;
            #pragma unroll 4
            for (int ks = 0; ks < 16; ks++) {
                uint32_t af[3][4], bf[4][2];
                #pragma unroll
                for (int mi = 0; mi < 3; mi++)
                    ldsm4(a_base + (uint32_t)mi * 16 * ASTRIDE + (uint32_t)ks * 32,
                          af[mi][0], af[mi][1], af[mi][2], af[mi][3]);
                ldsm4(b_base + (uint32_t)ks * 32, bf[0][0], bf[0][1], bf[1][0], bf[1][1]);
                ldsm4(b_base + 16u * ASTRIDE + (uint32_t)ks * 32,
                      bf[2][0], bf[2][1], bf[3][0], bf[3][1]);
                #pragma unroll
                for (int mi = 0; mi < 3; mi++)
                    #pragma unroll
                    for (int ni = 0; ni < 4; ni++)
                        mma16816(acc[mi][ni], af[mi], bf[ni]);
            }

            #pragma unroll
            for (int mi = 0; mi < 3; mi++) {
                #pragma unroll
                for (int h = 0; h < 2; h++) {
                    const int s = mi * 2 + h;
                    float tm = fmaxf(fmaxf(fmaxf(acc[mi][0][2*h], acc[mi][0][2*h+1]),
                                           fmaxf(acc[mi][1][2*h], acc[mi][1][2*h+1])),
                                     fmaxf(fmaxf(acc[mi][2][2*h], acc[mi][2][2*h+1]),
                                           fmaxf(acc[mi][3][2*h], acc[mi][3][2*h+1])));
                    if (tm <= cv2[s]) {
                        cv3[s] = fmaxf(cv3[s], tm);
                    } else {
                        #pragma unroll
                        for (int ni = 0; ni < 4; ni++) {
                            #pragma unroll
                            for (int c = 0; c < 2; c++) {
                                float v = acc[mi][ni][2 * h + c];
                                int kk = nt * BN + warp_n * 32 + ni * 8 + 2 * t + c;
                                if (v > cv1[s]) {
                                    cv3[s] = fmaxf(cv3[s], cv2[s]);
                                    cv2[s] = cv1[s]; ck2[s] = ck1[s];
                                    cv1[s] = v;      ck1[s] = kk;
                                } else if (v > cv2[s]) {
                                    cv3[s] = fmaxf(cv3[s], cv2[s]);
                                    cv2[s] = v;      ck2[s] = kk;
                                } else {
                                    cv3[s] = fmaxf(cv3[s], v);
                                }
                            }
                        }
                    }
                }
            }
            BAR1();
        }

        // merge + selection + recheck (HMMA rows only)
        float2* cand = (float2*)(smem + CAND_OFF);
        int* ovf_list = (int*)(smem + OVF_LIST_OFF);
        int* ovf_cnt  = (int*)(smem + OVF_CNT_OFF);
        const int wr = warp_n * 4 + t;
        #pragma unroll
        for (int mi = 0; mi < 3; mi++) {
            #pragma unroll
            for (int h = 0; h < 2; h++) {
                const int s = mi * 2 + h;
                int row = warp_m * 48 + mi * 16 + h * 8 + g;
                float2* p = cand + ((size_t)row * 16 + wr) * 3;
                p[0] = make_float2(cv1[s], __int_as_float(ck1[s]));
                p[1] = make_float2(cv2[s], __int_as_float(ck2[s]));
                p[2] = make_float2(cv3[s], __int_as_float(-1));
            }
        }
        if (tid == 0) *ovf_cnt = 0;
        BAR1();

        if (tid < BMH) {
            const int row = tid;
            const float2* p = cand + (size_t)row * 48;
            float rowmax = -CUDART_INF_F;
            for (int e = 0; e < 48; e++) rowmax = fmaxf(rowmax, p[e].x);
            const float th = rowmax - WINDOW;
            int sk[16]; int ns = 0; bool ovf = false;
            for (int e = 0; e < 48; e++) {
                if (p[e].x >= th) {
                    int k = __float_as_int(p[e].y);
                    if (k < 0) ovf = true;
                    else if (ns < 16) sk[ns++] = k;
                    else ovf = true;
                }
            }
            if (ovf) {
                int pos = atomicAdd(ovf_cnt, 1);
                ovf_list[pos] = row;
            } else {
                const int grow = rBase + row;
                int result = sk[0];
                if (ns > 1) {
                    const float arow = g_a[grow];
                    const float* xr = X + (size_t)grow * DIM;
                    float best = CUDART_INF_F; int bestk = 0x7fffffff;
                    for (int i = 0; i < ns; i++) {
                        int k = sk[i];
                        const float* wrp = W + (size_t)k * DIM;
                        float dot = 0.f;
                        #pragma unroll 8
                        for (int d = 0; d < DIM; d++) dot = fmaf(xr[d], wrp[d], dot);
                        float dist = fmaf(-2.f, dot, arow + g_c[k]);
                        if (dist < best || (dist == best && k < bestk)) { best = dist; bestk = k; }
                    }
                    result = bestk;
                }
                g_idx[grow] = result;
            }
        }
        BAR1();

        int cnt = *ovf_cnt;
        for (int oi = wid; oi < cnt; oi += 8) {
            int row = ovf_list[oi];
            int grow = rBase + row;
            const float* xr = X + (size_t)grow * DIM;
            float arow = g_a[grow];
            float best = CUDART_INF_F; int bestk = 0x7fffffff;
            for (int kb = lane * 4; kb < KCODES; kb += 128) {
                const float* w0 = W + (size_t)(kb + 0) * DIM;
                const float* w1 = W + (size_t)(kb + 1) * DIM;
                const float* w2 = W + (size_t)(kb + 2) * DIM;
                const float* w3 = W + (size_t)(kb + 3) * DIM;
                float d0 = 0.f, d1 = 0.f, d2 = 0.f, d3 = 0.f;
                for (int d = 0; d < DIM; d++) {
                    float xv = xr[d];
                    d0 = fmaf(xv, w0[d], d0); d1 = fmaf(xv, w1[d], d1);
                    d2 = fmaf(xv, w2[d], d2); d3 = fmaf(xv, w3[d], d3);
                }
                float dd[4];
                dd[0] = fmaf(-2.f, d0, arow + g_c[kb + 0]);
                dd[1] = fmaf(-2.f, d1, arow + g_c[kb + 1]);
                dd[2] = fmaf(-2.f, d2, arow + g_c[kb + 2]);
                dd[3] = fmaf(-2.f, d3, arow + g_c[kb + 3]);
                #pragma unroll
                for (int c = 0; c < 4; c++)
                    if (dd[c] < best || (dd[c] == best && (kb + c) < bestk)) { best = dd[c]; bestk = kb + c; }
            }
            #pragma unroll
            for (int off = 16; off; off >>= 1) {
                float ob = __shfl_xor_sync(0xffffffffu, best, off);
                int   ok = __shfl_xor_sync(0xffffffffu, bestk, off);
                if (ob < best || (ob == best && ok < bestk)) { best = ob; bestk = ok; }
            }
            if (lane == 0) g_idx[grow] = bestk;
        }
    } else {
        // ====== FFMA engine: rows rBase+96 .. rBase+127, bit-exact round-1 math ======
        const int ftid = tid - 256;          // 0..255
        const int tx = ftid & 15;            // code-group (8 codes)
        const int ty = ftid >> 4;            // row-group (2 rows)
        float* xs2 = (float*)(smem + FF_XS); // [16][132]
        float* ws2 = (float*)(smem + FF_WS); // [16][132]
        float* cs2 = (float*)(smem + FF_CS);
        float* rd2 = (float*)(smem + FF_RD);
        int*   rk2 = (int*)(smem + FF_RK);

        float a2[2];
        a2[0] = g_a[rBase + BMH + ty * 2 + 0];
        a2[1] = g_a[rBase + BMH + ty * 2 + 1];
        float bestD[2] = {CUDART_INF_F, CUDART_INF_F};
        int   bestK[2] = {0x3fffffff, 0x3fffffff};

        for (int kt = 0; kt < NTILES; kt++) {
            if (ftid < BN) cs2[ftid] = g_c[kt * BN + ftid];

            float acc[2][8];
            #pragma unroll
            for (int i = 0; i < 2; i++)
                #pragma unroll
                for (int j = 0; j < 8; j++) acc[i][j] = 0.f;

            for (int dc = 0; dc < DIM / 16; dc++) {
                if (ftid < 128) {
                    int row = ftid >> 2, seg = ftid & 3;
                    float4 v = *(const float4*)(X + (size_t)(rBase + BMH + row) * DIM + dc * 16 + seg * 4);
                    xs2[(seg * 4 + 0) * 132 + row] = v.x;
                    xs2[(seg * 4 + 1) * 132 + row] = v.y;
                    xs2[(seg * 4 + 2) * 132 + row] = v.z;
                    xs2[(seg * 4 + 3) * 132 + row] = v.w;
                }
                #pragma unroll
                for (int h = 0; h < 2; h++) {
                    int idx = ftid + h * 256;
                    int row = idx >> 2, seg = idx & 3;
                    float4 u = *(const float4*)(W + (size_t)(kt * BN + row) * DIM + dc * 16 + seg * 4);
                    ws2[(seg * 4 + 0) * 132 + row] = u.x;
                    ws2[(seg * 4 + 1) * 132 + row] = u.y;
                    ws2[(seg * 4 + 2) * 132 + row] = u.z;
                    ws2[(seg * 4 + 3) * 132 + row] = u.w;
                }
                BAR2();
                #pragma unroll
                for (int d = 0; d < 16; d++) {
                    float2 xa = *(const float2*)&xs2[d * 132 + ty * 2];
                    float4 wa = *(const float4*)&ws2[d * 132 + tx * 4];
                    float4 wb = *(const float4*)&ws2[d * 132 + 64 + tx * 4];
                    float wf[8] = {wa.x, wa.y, wa.z, wa.w, wb.x, wb.y, wb.z, wb.w};
                    #pragma unroll
                    for (int j = 0; j < 8; j++) {
                        acc[0][j] = fmaf(xa.x, wf[j], acc[0][j]);
                        acc[1][j] = fmaf(xa.y, wf[j], acc[1][j]);
                    }
                }
                BAR2();
            }

            #pragma unroll
            for (int i = 0; i < 2; i++) {
                #pragma unroll
                for (int j = 0; j < 8; j++) {
                    int kl = (j < 4) ? (tx * 4 + j) : (64 + tx * 4 + (j - 4));
                    float t0 = a2[i] + cs2[kl];
                    float dist = fmaf(-2.f, acc[i][j], t0);
                    int k = kt * BN + kl;
                    if (dist < bestD[i] || (dist == bestD[i] && k < bestK[i])) {
                        bestD[i] = dist; bestK[i] = k;
                    }
                }
            }
            BAR2();   // protect cs2 before next tile's write
        }

        if (ftid < BMF) { rd2[ftid] = CUDART_INF_F; rk2[ftid] = 0x3fffffff; }
        BAR2();
        for (int t = 0; t < 16; t++) {
            if (tx == t) {
                #pragma unroll
                for (int i = 0; i < 2; i++) {
                    int r = ty * 2 + i;
                    if (bestD[i] < rd2[r] || (bestD[i] == rd2[r] && bestK[i] < rk2[r])) {
                        rd2[r] = bestD[i]; rk2[r] = bestK[i];
                    }
                }
            }
            BAR2();
        }
        if (ftid < BMF) g_idx[rBase + BMH + ftid] = rk2[ftid];
    }
}

// ---------------- gather ----------------
__global__ void vq_gather_kernel(const float* __restrict__ W,
                                 float* __restrict__ out,
                                 float* __restrict__ out_idx) {
    int warp = (blockIdx.x * blockDim.x + threadIdx.x) >> 5;
    int lane = threadIdx.x & 31;
    if (warp >= NROWS) return;
    int k = g_idx[warp];
    const float4* src = (const float4*)(W + (size_t)k * DIM);
    float4* dst = (float4*)(out + (size_t)warp * DIM);
    dst[lane]      = src[lane];
    dst[lane + 32] = src[lane + 32];
    if (out_idx != nullptr && lane == 0) out_idx[warp] = (float)k;
}

// ---------------- launcher ----------------
extern "C" void kernel_launch(void* const* d_in, const int* in_sizes, int n_in,
                              void* d_out, int out_size) {
    const float* X = (const float*)d_in[0];
    const float* W = (const float*)d_in[1];
    if (n_in >= 2 && in_sizes[0] == KCODES * DIM && in_sizes[1] == NROWS * DIM) {
        W = (const float*)d_in[0];
        X = (const float*)d_in[1];
    }
    float* out = (float*)d_out;

    float* pa = nullptr; float* pc = nullptr;
    __half* pxh = nullptr; __half* pwh = nullptr;
    cudaGetSymbolAddress((void**)&pa, g_a);
    cudaGetSymbolAddress((void**)&pc, g_c);
    cudaGetSymbolAddress((void**)&pxh, g_xh);
    cudaGetSymbolAddress((void**)&pwh, g_wh);

    cudaFuncSetAttribute(vq_screen, cudaFuncAttributeMaxDynamicSharedMemorySize, SMEM_TOTAL);

    vq_prep_x<<<NROWS / 8, 256>>>(X, pa, pxh);
    vq_prep_w<<<KCODES / 8, 256>>>(W, pc, pwh);
    vq_screen<<<NROWS / BMT, 512, SMEM_TOTAL>>>(X, W, pxh, pwh);

    float* out_idx = (out_size >= NROWS * DIM + NROWS) ? (out + (size_t)NROWS * DIM) : nullptr;
    vq_gather_kernel<<<NROWS / 8, 256>>>(W, out, out_idx);
}